// round 11
// baseline (speedup 1.0000x reference)
#include <cuda_runtime.h>
#include <cuda_fp16.h>

// Problem: B=4, D=64, K=32, N=8192. Total floats = 2,097,152 = 524288 float4.
#define Kk 32
#define Dk 64
#define TPB 256
#define GRIDA 2048           // encode: 1 float4/thread; blk = bd*8 + chunk
#define GRIDC 512            // scale:  4 float4/thread; blk = bd*2 + chunk

typedef unsigned long long u64;
typedef unsigned int u32;

__device__ float g_partial[GRIDA];   // per-block sum of E (deterministic)

// ---- fp32 packed helpers ----
__device__ __forceinline__ u64 pk(float lo, float hi) {
    u64 r; asm("mov.b64 %0, {%1,%2};" : "=l"(r) : "f"(lo), "f"(hi)); return r;
}
__device__ __forceinline__ u64 pku(u32 lo, u32 hi) {
    u64 r; asm("mov.b64 %0, {%1,%2};" : "=l"(r) : "r"(lo), "r"(hi)); return r;
}
__device__ __forceinline__ void upk(float& lo, float& hi, u64 v) {
    asm("mov.b64 {%0,%1}, %2;" : "=f"(lo), "=f"(hi) : "l"(v));
}
__device__ __forceinline__ u64 mul2(u64 a, u64 b) {
    u64 r; asm("mul.rn.f32x2 %0, %1, %2;" : "=l"(r) : "l"(a), "l"(b)); return r;
}
__device__ __forceinline__ u64 fma2(u64 a, u64 b, u64 c) {
    u64 r; asm("fma.rn.f32x2 %0, %1, %2, %3;" : "=l"(r) : "l"(a), "l"(b), "l"(c)); return r;
}

// ---- fp16x2 helpers (carried in u32) ----
__device__ __forceinline__ u32 cvt2h(float hi, float lo) {   // {lo, hi}
    u32 r; asm("cvt.rn.f16x2.f32 %0, %1, %2;" : "=r"(r) : "f"(hi), "f"(lo)); return r;
}
__device__ __forceinline__ u32 hex2(u32 a) {                 // 2 exps, 1 MUFU op
    u32 r; asm("ex2.approx.f16x2 %0, %1;" : "=r"(r) : "r"(a)); return r;
}
__device__ __forceinline__ u32 hadd2(u32 a, u32 b) {
    u32 r; asm("add.rn.f16x2 %0, %1, %2;" : "=r"(r) : "r"(a), "r"(b)); return r;
}
__device__ __forceinline__ u32 hfma2(u32 a, u32 b, u32 c) {
    u32 r; asm("fma.rn.f16x2 %0, %1, %2, %3;" : "=r"(r) : "r"(a), "r"(b), "r"(c)); return r;
}
__device__ __forceinline__ float lo2f(u32 h) {
    float f; asm("{.reg .f16 l,h; mov.b32 {l,h}, %1; cvt.f32.f16 %0, l;}" : "=f"(f) : "r"(h)); return f;
}
__device__ __forceinline__ float hi2f(u32 h) {
    float f; asm("{.reg .f16 l,h; mov.b32 {l,h}, %1; cvt.f32.f16 %0, h;}" : "=f"(f) : "r"(h)); return f;
}

// ---- Kernel A: E (unscaled) + per-block partial sums (UNCHANGED from R10) ----
// E[n] = x + (sum_k e_k * (-c_k)) / (sum_k e_k),  e_k = exp2(slx*x^2 + p1*x + p0)
__global__ void __launch_bounds__(TPB)
k_encode(const float* __restrict__ X, const float* __restrict__ cw,
         const float* __restrict__ sc, float* __restrict__ out)
{
    __shared__ uint4 s_cA[Kk];   // (p1,p1,p0,p0) fp32 bits
    __shared__ uint4 s_cB[Kk];   // (sl,sl,hc,hc) fp32,fp32,half2,half2
    __shared__ float s_red[TPB / 32];

    const int t   = threadIdx.x;
    const int blk = blockIdx.x;
    const int d   = (blk >> 3) & 63;

    if (t < Kk) {
        const float c   = cw[t * Dk + d];
        const float slx = sc[t * Dk + d] * 1.4426950408889634f;  // fold log2(e)
        const u32 p1 = __float_as_uint(-2.0f * c * slx);
        const u32 p0 = __float_as_uint(c * c * slx);
        const u32 sl = __float_as_uint(slx);
        const u32 hc = cvt2h(-c, -c);                            // half2(-c,-c)
        s_cA[t] = make_uint4(p1, p1, p0, p0);
        s_cB[t] = make_uint4(sl, sl, hc, hc);
    }
    __syncthreads();

    const float4 v = ((const float4*)X)[blk * TPB + t];
    const u64 xa = pk(v.x, v.y), xb = pk(v.z, v.w);
    const u64 xxa = mul2(xa, xa), xxb = mul2(xb, xb);
    u32 da = 0u, db = 0u, wa = 0u, wb = 0u;     // half2 accumulators

    #pragma unroll 8
    for (int k = 0; k < Kk; k++) {
        const uint4 cA = s_cA[k];               // LDS.128 broadcast
        const uint4 cB = s_cB[k];               // LDS.128 broadcast
        const u64 p1 = pku(cA.x, cA.y), p0 = pku(cA.z, cA.w);
        const u64 sl = pku(cB.x, cB.y);
        const u32 hc = cB.z;
        const u64 a0 = fma2(sl, xxa, fma2(p1, xa, p0));   // fp32 args (<= 0)
        const u64 a1 = fma2(sl, xxb, fma2(p1, xb, p0));
        float l0, h0, l1, h1;
        upk(l0, h0, a0);                        // free (register aliasing)
        upk(l1, h1, a1);
        const u32 e0 = hex2(cvt2h(h0, l0));     // 2 exps per MUFU op
        const u32 e1 = hex2(cvt2h(h1, l1));
        da = hadd2(da, e0);  wa = hfma2(e0, hc, wa);      // w = sum e*(-c)
        db = hadd2(db, e1);  wb = hfma2(e1, hc, wb);
    }

    float4 o;                                   // E = x + w/den
    o.x = v.x + __fdividef(lo2f(wa), lo2f(da));
    o.y = v.y + __fdividef(hi2f(wa), hi2f(da));
    o.z = v.z + __fdividef(lo2f(wb), lo2f(db));
    o.w = v.w + __fdividef(hi2f(wb), hi2f(db));
    ((float4*)out)[blk * TPB + t] = o;          // unscaled E; k_scale rescales

    float ssum = (o.x + o.y) + (o.z + o.w);
    #pragma unroll
    for (int off = 16; off > 0; off >>= 1)
        ssum += __shfl_xor_sync(0xffffffffu, ssum, off);
    if ((t & 31) == 0) s_red[t >> 5] = ssum;
    __syncthreads();
    if (t == 0) {
        float s = 0.f;
        #pragma unroll
        for (int w = 0; w < TPB / 32; w++) s += s_red[w];
        g_partial[blk] = s;
    }
}

// ---- Kernel B: deep-MLP scale; gamma chain parallelized & overlapped ----
__global__ void __launch_bounds__(TPB)
k_scale(const float* __restrict__ fw, const float* __restrict__ fb,
        float* __restrict__ out)
{
    __shared__ float s_eg[256];     // Eglob[b*64+j] / K (all 256, parallel build)
    __shared__ float s_g;

    const int t   = threadIdx.x;
    const int blk = blockIdx.x;
    const int bd  = blk >> 1;       // 2 blocks per (b,d) plane
    const int d   = bd & 63;
    const int b   = bd >> 6;

    // Issue ALL E loads first (4 float4 in flight per thread).
    float4* base = (float4*)out + blk * 1024;
    float4 e[4];
    #pragma unroll
    for (int i = 0; i < 4; i++) e[i] = __ldcg(base + i * TPB + t);

    // Parallel Eglob: each thread sums 8 partials for its (b,j) = t.
    {
        const float* gp = &g_partial[t * 8];
        float s = 0.f;
        #pragma unroll
        for (int r = 0; r < 8; r++) s += __ldcg(gp + r);
        s_eg[t] = s * (1.0f / Kk);
    }
    __syncthreads();

    // Warp 0: dot(Eglob[b,:], fw[d,:]) -> gamma
    if (t < 32) {
        const float* eg = s_eg + b * Dk;
        float acc = eg[t] * __ldg(fw + d * Dk + t)
                  + eg[t + 32] * __ldg(fw + d * Dk + t + 32);
        #pragma unroll
        for (int off = 16; off > 0; off >>= 1)
            acc += __shfl_xor_sync(0xffffffffu, acc, off);
        if (t == 0)
            s_g = 1.f + 1.f / (1.f + __expf(-(acc + __ldg(fb + d))));  // 1+sigmoid
    }
    __syncthreads();

    const float g = s_g;
    #pragma unroll
    for (int i = 0; i < 4; i++) {
        float4 o;
        o.x = fmaxf(e[i].x * g, 0.f); o.y = fmaxf(e[i].y * g, 0.f);
        o.z = fmaxf(e[i].z * g, 0.f); o.w = fmaxf(e[i].w * g, 0.f);
        base[i * TPB + t] = o;
    }
}

extern "C" void kernel_launch(void* const* d_in, const int* in_sizes, int n_in,
                              void* d_out, int out_size)
{
    const float* X   = (const float*)d_in[0];  // (B,D,T,H,W)
    const float* cw  = (const float*)d_in[1];  // (K,D)
    const float* sc  = (const float*)d_in[2];  // (K,D)
    const float* fcw = (const float*)d_in[3];  // (D,D)
    const float* fcb = (const float*)d_in[4];  // (D,)
    float* out = (float*)d_out;

    k_encode<<<GRIDA, TPB>>>(X, cw, sc, out);
    k_scale<<<GRIDC, TPB>>>(fcw, fcb, out);
}